// round 1
// baseline (speedup 1.0000x reference)
#include <cuda_runtime.h>
#include <cstdint>
#include <math.h>

typedef unsigned long long ull;

#define BB 128
#define SS 2048
#define QQ 1000
#define KK 5
#define MM 50
#define DK 64
#define DV 128

// ---------------- device scratch / tables ----------------
__device__ float g_attn[QQ * 52];          // softmax(q_e @ key^T), row padded to 52 (16B multiple)
__device__ float4 g_ea[QQ * KK * DV];      // per (q,r,v): (-erase, -erase, add, add)
__device__ int2  g_off[BB * SS];           // {q*52 (attn float off), (q*5+r)*128 (ea float4 off)}
__device__ float g_qsum[QQ * 64];          // q_e @ summary_w[128:] + summary_b, j padded to 64
__device__ float g_alpha[QQ];
__device__ float g_beta[QQ * 4];
__device__ ull   g_wt2[DV * 32];           // summary_w[:128] packed float2 over j-pairs (64 j, pad 0)
__device__ float g_thw[64];                // theta_w padded to 64 with zeros
__device__ float g_read[BB * SS * DV];     // 134MB read scratch

// ---------------- f32x2 helpers ----------------
__device__ __forceinline__ ull pack2(float x, float y) {
    ull u; asm("mov.b64 %0, {%1, %2};" : "=l"(u) : "f"(x), "f"(y)); return u;
}
__device__ __forceinline__ float2 u2f(ull u) {
    float2 v; asm("mov.b64 {%0, %1}, %2;" : "=f"(v.x), "=f"(v.y) : "l"(u)); return v;
}
__device__ __forceinline__ ull ffma2(ull a, ull b, ull c) {
    ull d; asm("fma.rn.f32x2 %0, %1, %2, %3;" : "=l"(d) : "l"(a), "l"(b), "l"(c)); return d;
}
__device__ __forceinline__ float tanh_fast(float x) {
    float e = __expf(2.f * x);
    return 1.f - 2.f / (e + 1.f);
}

// ---------------- kernel A: per-question tables ----------------
__global__ void kA(const float* __restrict__ qew, const float* __restrict__ key_mem,
                   const float* __restrict__ sw, const float* __restrict__ sb,
                   const float* __restrict__ aw, const float* __restrict__ ab,
                   const float* __restrict__ bw, const float* __restrict__ bb) {
    int q = blockIdx.x;
    int t = threadIdx.x;  // 64 threads
    __shared__ float qe[64];
    __shared__ float sl[64];
    qe[t] = qew[q * DK + t];
    __syncthreads();

    float lg = -1e30f;
    if (t < MM) {
        const float* kr = key_mem + t * DK;
        float s = 0.f;
        #pragma unroll
        for (int k = 0; k < DK; k++) s += qe[k] * kr[k];
        lg = s;
    }
    sl[t] = lg;
    __syncthreads();
    float mx = -1e30f;
    for (int i = 0; i < MM; i++) mx = fmaxf(mx, sl[i]);
    float e = (t < MM) ? expf(sl[t] - mx) : 0.f;
    __syncthreads();
    sl[t] = e;
    __syncthreads();
    float sm = 0.f;
    for (int i = 0; i < MM; i++) sm += sl[i];
    if (t < 52) g_attn[q * 52 + t] = (t < MM) ? (e / sm) : 0.f;

    // qsum (padded to 64)
    float qs = 0.f;
    if (t < 50) {
        float s = sb[t];
        #pragma unroll
        for (int k = 0; k < DK; k++) s += qe[k] * sw[(128 + k) * 50 + t];
        qs = s;
    }
    g_qsum[q * 64 + t] = qs;

    if (t == 0) {
        float s = ab[0];
        #pragma unroll
        for (int k = 0; k < DK; k++) s += qe[k] * aw[k];
        g_alpha[q] = (s > 20.f) ? s : log1pf(expf(s));  // softplus
    }
    if (t < 4) {
        float s = bb[t];
        #pragma unroll
        for (int k = 0; k < DK; k++) s += qe[k] * bw[k * 4 + t];
        g_beta[q * 4 + t] = s;
    }
}

// ---------------- kernel B: per-(q,r) erase/add tables ----------------
__global__ void kB(const float* __restrict__ iew, const float* __restrict__ vpw,
                   const float* __restrict__ vpb, const float* __restrict__ ew,
                   const float* __restrict__ eb, const float* __restrict__ aw2,
                   const float* __restrict__ ab2) {
    int qr = blockIdx.x;
    int q = qr / 5, r = qr % 5;
    int v = threadIdx.x;  // 128 threads
    __shared__ float iv[64];
    __shared__ float rf[5];
    __shared__ float ve[128];
    if (v < 64) iv[v] = iew[q * DK + v];
    if (v < 5)  rf[v] = fmaxf(0.f, 1.f - fabsf((float)(v - r)) * 0.25f);
    __syncthreads();
    float s = vpb[v];
    #pragma unroll
    for (int k = 0; k < 64; k++) s += iv[k] * vpw[k * 128 + v];
    #pragma unroll
    for (int c = 0; c < 5; c++) s += rf[c] * vpw[(64 + c) * 128 + v];
    ve[v] = s;
    __syncthreads();
    float se = eb[v], sa = ab2[v];
    for (int i = 0; i < 128; i++) {
        float x = ve[i];
        se += x * ew[i * 128 + v];
        sa += x * aw2[i * 128 + v];
    }
    float e = 1.f / (1.f + expf(-se));
    float a = tanhf(sa);
    g_ea[qr * 128 + v] = make_float4(-e, -e, a, a);
}

// ---------------- kernel C: per-(b,s) offsets ----------------
__global__ void kC(const int* __restrict__ questions, const int* __restrict__ responses) {
    int p = blockIdx.x * blockDim.x + threadIdx.x;
    if (p >= BB * SS) return;
    int q = questions[p], r = responses[p];
    g_off[p] = make_int2(q * 52, (q * 5 + r) * 128);
}

// ---------------- kernel W: pack summary_w / theta_w ----------------
__global__ void kW(const float* __restrict__ sw, const float* __restrict__ tw) {
    int idx = blockIdx.x * blockDim.x + threadIdx.x;
    if (idx < DV * 32) {
        int v = idx >> 5, jp = idx & 31;
        int j0 = 2 * jp, j1 = 2 * jp + 1;
        float w0 = (j0 < 50) ? sw[v * 50 + j0] : 0.f;
        float w1 = (j1 < 50) ? sw[v * 50 + j1] : 0.f;
        ((float2*)g_wt2)[idx] = make_float2(w0, w1);
    } else if (idx < DV * 32 + 64) {
        int j = idx - DV * 32;
        g_thw[j] = (j < 50) ? tw[j] : 0.f;
    }
}

// ---------------- scan kernel ----------------
__device__ __forceinline__ void pf_step(ull* a, float4& ea, int2 off, int v) {
    const uint4* ap = reinterpret_cast<const uint4*>(g_attn + off.x);
    uint4* dst = reinterpret_cast<uint4*>(a);
    #pragma unroll
    for (int i = 0; i < 13; i++) dst[i] = __ldg(ap + i);
    ea = __ldg(&g_ea[off.y + v]);
}

__device__ __forceinline__ float step_compute(const ull* a, float4 ea, ull* mem2) {
    ull e2 = pack2(ea.x, ea.y);   // (-e,-e)
    ull d2 = pack2(ea.z, ea.w);   // (a,a)
    ull r0 = 0ull, r1 = 0ull;
    #pragma unroll
    for (int i = 0; i < 25; i++) {
        ull ai = a[i];
        if (i & 1) r1 = ffma2(ai, mem2[i], r1);
        else       r0 = ffma2(ai, mem2[i], r0);
        ull t = ffma2(e2, mem2[i], d2);      // add - erase*mem
        mem2[i] = ffma2(ai, t, mem2[i]);     // mem += attn*t
    }
    float2 f0 = u2f(r0), f1 = u2f(r1);
    return (f0.x + f1.x) + (f0.y + f1.y);
}

__global__ void __launch_bounds__(128) kScan(const float* __restrict__ init_mem) {
    int b = blockIdx.x;
    int v = threadIdx.x;

    ull mem2[25];
    #pragma unroll
    for (int i = 0; i < 25; i++)
        mem2[i] = pack2(init_mem[(2 * i) * DV + v], init_mem[(2 * i + 1) * DV + v]);

    const int2* offp = g_off + b * SS;
    alignas(16) ull A[26];
    alignas(16) ull B[26];
    float4 eaA, eaB;

    int2 o0 = __ldg(offp);
    pf_step(A, eaA, o0, v);
    int2 o1 = __ldg(offp + 1);
    int2 o2 = __ldg(offp + 2);

    float* outp = g_read + (size_t)b * SS * DV + v;

    #pragma unroll 1
    for (int s = 0; s < SS; s += 2) {
        pf_step(B, eaB, o1, v);                        // fetch step s+1
        int i3 = s + 3; if (i3 > SS - 1) i3 = SS - 1;
        int2 o3 = __ldg(offp + i3);
        float rd0 = step_compute(A, eaA, mem2);        // compute step s
        outp[0] = rd0;

        pf_step(A, eaA, o2, v);                        // fetch step s+2
        int i4 = s + 4; if (i4 > SS - 1) i4 = SS - 1;
        int2 o4 = __ldg(offp + i4);
        float rd1 = step_compute(B, eaB, mem2);        // compute step s+1
        outp[DV] = rd1;

        outp += 2 * DV;
        o1 = o3; o2 = o4;
    }
}

// ---------------- epilogue kernel ----------------
// output layout (flat concatenation of reference tuple):
#define NPOS (BB * SS)
#define OFF_THETA  0
#define OFF_ALPHA  (NPOS)
#define OFF_BETA   (2 * NPOS)
#define OFF_LOGITS (6 * NPOS)
#define OFF_PROBS  (11 * NPOS)

__global__ void __launch_bounds__(128) kEpi(const int* __restrict__ questions,
                                            const float* __restrict__ theta_b,
                                            float* __restrict__ out) {
    int tid = threadIdx.x;
    int pt = tid >> 3;        // 0..15, 4 positions each
    int jt = tid & 7;         // 0..7, 4 j-pairs each (covers j 0..63, padded)
    int pos0 = blockIdx.x * 64 + pt * 4;

    ull acc[4][4];
    #pragma unroll
    for (int k = 0; k < 4; k++)
        #pragma unroll
        for (int c = 0; c < 4; c++) acc[k][c] = 0ull;

    const float4* rp0 = (const float4*)(g_read + (size_t)(pos0 + 0) * DV);
    const float4* rp1 = (const float4*)(g_read + (size_t)(pos0 + 1) * DV);
    const float4* rp2 = (const float4*)(g_read + (size_t)(pos0 + 2) * DV);
    const float4* rp3 = (const float4*)(g_read + (size_t)(pos0 + 3) * DV);

    #pragma unroll 4
    for (int v4 = 0; v4 < 32; v4++) {
        float4 rd[4];
        rd[0] = __ldg(rp0 + v4);
        rd[1] = __ldg(rp1 + v4);
        rd[2] = __ldg(rp2 + v4);
        rd[3] = __ldg(rp3 + v4);
        #pragma unroll
        for (int d = 0; d < 4; d++) {
            int v = v4 * 4 + d;
            const ulonglong2* wr = (const ulonglong2*)(g_wt2 + v * 32 + jt * 4);
            ulonglong2 wA = __ldg(wr);
            ulonglong2 wB = __ldg(wr + 1);
            #pragma unroll
            for (int k = 0; k < 4; k++) {
                float rv = ((const float*)&rd[k])[d];
                ull rvv = pack2(rv, rv);
                acc[k][0] = ffma2(rvv, wA.x, acc[k][0]);
                acc[k][1] = ffma2(rvv, wA.y, acc[k][1]);
                acc[k][2] = ffma2(rvv, wB.x, acc[k][2]);
                acc[k][3] = ffma2(rvv, wB.y, acc[k][3]);
            }
        }
    }

    float tb = __ldg(theta_b);
    #pragma unroll
    for (int k = 0; k < 4; k++) {
        int pos = pos0 + k;
        int q = __ldg(questions + pos);
        const ull* qs2 = ((const ull*)g_qsum) + q * 32 + jt * 4;
        float th = 0.f;
        #pragma unroll
        for (int c = 0; c < 4; c++) {
            float2 s2 = u2f(acc[k][c]);
            float2 qv = u2f(__ldg(qs2 + c));
            int jp = jt * 4 + c;
            float s0 = tanh_fast(s2.x + qv.x);
            float s1 = tanh_fast(s2.y + qv.y);
            th += s0 * g_thw[2 * jp] + s1 * g_thw[2 * jp + 1];
        }
        // reduce over the 8 jt lanes (contiguous in-warp group)
        th += __shfl_xor_sync(0xffffffffu, th, 1);
        th += __shfl_xor_sync(0xffffffffu, th, 2);
        th += __shfl_xor_sync(0xffffffffu, th, 4);
        if (jt == 0) {
            float theta = tanhf(th + tb);
            float alpha = __ldg(g_alpha + q);
            float4 bv = __ldg((const float4*)(g_beta + q * 4));
            float it = theta * alpha;
            float l0 = 0.f;
            float l1 = it - bv.x;
            float l2 = l1 + it - bv.y;
            float l3 = l2 + it - bv.z;
            float l4 = l3 + it - bv.w;
            float m = fmaxf(fmaxf(fmaxf(l0, l1), fmaxf(l2, l3)), l4);
            float e0 = __expf(l0 - m), e1 = __expf(l1 - m), e2 = __expf(l2 - m),
                  e3 = __expf(l3 - m), e4 = __expf(l4 - m);
            float inv = 1.f / (e0 + e1 + e2 + e3 + e4);
            out[OFF_THETA + pos] = theta;
            out[OFF_ALPHA + pos] = alpha;
            ((float4*)(out + OFF_BETA))[pos] = bv;
            float* lo = out + OFF_LOGITS + pos * 5;
            lo[0] = l0; lo[1] = l1; lo[2] = l2; lo[3] = l3; lo[4] = l4;
            float* pr = out + OFF_PROBS + pos * 5;
            pr[0] = e0 * inv; pr[1] = e1 * inv; pr[2] = e2 * inv;
            pr[3] = e3 * inv; pr[4] = e4 * inv;
        }
    }
}

// ---------------- launch ----------------
extern "C" void kernel_launch(void* const* d_in, const int* in_sizes, int n_in,
                              void* d_out, int out_size) {
    const int*   questions    = (const int*)d_in[0];
    const int*   responses    = (const int*)d_in[1];
    const float* q_embed_w    = (const float*)d_in[2];
    const float* item_embed_w = (const float*)d_in[3];
    const float* value_proj_w = (const float*)d_in[4];
    const float* value_proj_b = (const float*)d_in[5];
    const float* key_mem      = (const float*)d_in[6];
    const float* init_mem     = (const float*)d_in[7];
    const float* erase_w      = (const float*)d_in[8];
    const float* erase_b      = (const float*)d_in[9];
    const float* add_w        = (const float*)d_in[10];
    const float* add_b        = (const float*)d_in[11];
    const float* summary_w    = (const float*)d_in[12];
    const float* summary_b    = (const float*)d_in[13];
    const float* theta_w      = (const float*)d_in[14];
    const float* theta_b      = (const float*)d_in[15];
    const float* alpha_w      = (const float*)d_in[16];
    const float* alpha_b      = (const float*)d_in[17];
    const float* beta_w       = (const float*)d_in[18];
    const float* beta_b       = (const float*)d_in[19];
    float* out = (float*)d_out;

    kA<<<QQ, 64>>>(q_embed_w, key_mem, summary_w, summary_b,
                   alpha_w, alpha_b, beta_w, beta_b);
    kB<<<QQ * KK, 128>>>(item_embed_w, value_proj_w, value_proj_b,
                         erase_w, erase_b, add_w, add_b);
    kC<<<(BB * SS + 255) / 256, 256>>>(questions, responses);
    kW<<<(DV * 32 + 64 + 255) / 256, 256>>>(summary_w, theta_w);
    kScan<<<BB, 128>>>(init_mem);
    kEpi<<<(BB * SS) / 64, 128>>>(questions, theta_b, out);
}

// round 2
// speedup vs baseline: 1.1178x; 1.1178x over previous
#include <cuda_runtime.h>
#include <cstdint>
#include <math.h>

typedef unsigned long long ull;

#define BB 128
#define SS 2048
#define QQ 1000
#define KK 5
#define MM 50
#define DK 64
#define DV 128
#define STAGES 4

// ---------------- device scratch / tables ----------------
__device__ float g_attn[QQ * 52];          // softmax(q_e @ key^T), row padded to 52 (16B multiple)
__device__ float4 g_ea[QQ * KK * DV];      // per (q,r,v): (-erase, -erase, add, add)
__device__ float g_qsum[QQ * 64];          // q_e @ summary_w[128:] + summary_b, j padded to 64
__device__ float g_alpha[QQ];
__device__ float g_beta[QQ * 4];
__device__ ull   g_wt2[DV * 32];           // summary_w[:128] packed float2 over j-pairs (64 j, pad 0)
__device__ float g_thw[64];                // theta_w padded to 64 with zeros
__device__ float g_read[BB * SS * DV];     // 134MB read scratch

// ---------------- f32x2 helpers ----------------
__device__ __forceinline__ ull pack2(float x, float y) {
    ull u; asm("mov.b64 %0, {%1, %2};" : "=l"(u) : "f"(x), "f"(y)); return u;
}
__device__ __forceinline__ float2 u2f(ull u) {
    float2 v; asm("mov.b64 {%0, %1}, %2;" : "=f"(v.x), "=f"(v.y) : "l"(u)); return v;
}
__device__ __forceinline__ ull ffma2(ull a, ull b, ull c) {
    ull d; asm("fma.rn.f32x2 %0, %1, %2, %3;" : "=l"(d) : "l"(a), "l"(b), "l"(c)); return d;
}
__device__ __forceinline__ float tanh_fast(float x) {
    float e = __expf(2.f * x);
    return 1.f - 2.f / (e + 1.f);
}
__device__ __forceinline__ void cp16(void* smem_dst, const void* gsrc) {
    unsigned s = (unsigned)__cvta_generic_to_shared(smem_dst);
    asm volatile("cp.async.ca.shared.global [%0], [%1], 16;\n" :: "r"(s), "l"(gsrc));
}

// ---------------- kernel A: per-question tables ----------------
__global__ void kA(const float* __restrict__ qew, const float* __restrict__ key_mem,
                   const float* __restrict__ sw, const float* __restrict__ sb,
                   const float* __restrict__ aw, const float* __restrict__ ab,
                   const float* __restrict__ bw, const float* __restrict__ bb) {
    int q = blockIdx.x;
    int t = threadIdx.x;  // 64 threads
    __shared__ float qe[64];
    __shared__ float sl[64];
    qe[t] = qew[q * DK + t];
    __syncthreads();

    float lg = -1e30f;
    if (t < MM) {
        const float* kr = key_mem + t * DK;
        float s = 0.f;
        #pragma unroll
        for (int k = 0; k < DK; k++) s += qe[k] * kr[k];
        lg = s;
    }
    sl[t] = lg;
    __syncthreads();
    float mx = -1e30f;
    for (int i = 0; i < MM; i++) mx = fmaxf(mx, sl[i]);
    float e = (t < MM) ? expf(sl[t] - mx) : 0.f;
    __syncthreads();
    sl[t] = e;
    __syncthreads();
    float sm = 0.f;
    for (int i = 0; i < MM; i++) sm += sl[i];
    if (t < 52) g_attn[q * 52 + t] = (t < MM) ? (e / sm) : 0.f;

    // qsum (padded to 64)
    float qs = 0.f;
    if (t < 50) {
        float s = sb[t];
        #pragma unroll
        for (int k = 0; k < DK; k++) s += qe[k] * sw[(128 + k) * 50 + t];
        qs = s;
    }
    g_qsum[q * 64 + t] = qs;

    if (t == 0) {
        float s = ab[0];
        #pragma unroll
        for (int k = 0; k < DK; k++) s += qe[k] * aw[k];
        g_alpha[q] = (s > 20.f) ? s : log1pf(expf(s));  // softplus
    }
    if (t < 4) {
        float s = bb[t];
        #pragma unroll
        for (int k = 0; k < DK; k++) s += qe[k] * bw[k * 4 + t];
        g_beta[q * 4 + t] = s;
    }
}

// ---------------- kernel B: per-question erase/add tables (all 5 responses) ----------------
__global__ void __launch_bounds__(128) kB(const float* __restrict__ iew, const float* __restrict__ vpw,
                   const float* __restrict__ vpb, const float* __restrict__ ew,
                   const float* __restrict__ eb, const float* __restrict__ aw2,
                   const float* __restrict__ ab2) {
    int q = blockIdx.x;
    int v = threadIdx.x;  // 128 threads, thread = v (output dim)
    __shared__ float iv[64];
    __shared__ float ve_sh[128][8];  // [i][r], r padded to 8 floats (pairs aligned)
    if (v < 64) iv[v] = iew[q * DK + v];
    __syncthreads();

    // value_embed base = item part + bias (same for all responses)
    float base = vpb[v];
    #pragma unroll
    for (int k = 0; k < 64; k++) base += iv[k] * vpw[k * 128 + v];
    // response-feature columns
    float c0 = vpw[(64 + 0) * 128 + v];
    float c1 = vpw[(64 + 1) * 128 + v];
    float c2 = vpw[(64 + 2) * 128 + v];
    float c3 = vpw[(64 + 3) * 128 + v];
    float c4 = vpw[(64 + 4) * 128 + v];
    float col[5] = {c0, c1, c2, c3, c4};
    #pragma unroll
    for (int r = 0; r < 5; r++) {
        float s = base;
        #pragma unroll
        for (int c = 0; c < 5; c++) {
            float d = fabsf((float)(c - r)) * 0.25f;
            float rf = fmaxf(0.f, 1.f - d);
            s += rf * col[c];
        }
        ve_sh[v][r] = s;
    }
    __syncthreads();

    // erase/add GEMVs for all 5 responses at once, f32x2 over response pairs
    float ebv = eb[v], abv = ab2[v];
    ull se01 = pack2(ebv, ebv), se23 = pack2(ebv, ebv); float se4 = ebv;
    ull sa01 = pack2(abv, abv), sa23 = pack2(abv, abv); float sa4 = abv;
    #pragma unroll 4
    for (int i = 0; i < 128; i++) {
        float we = ew[i * 128 + v];
        float wa = aw2[i * 128 + v];
        ull we2 = pack2(we, we), wa2 = pack2(wa, wa);
        const ull* vr = (const ull*)ve_sh[i];
        ull x01 = vr[0], x23 = vr[1];
        float x4 = ve_sh[i][4];
        se01 = ffma2(x01, we2, se01);
        se23 = ffma2(x23, we2, se23);
        se4  = fmaf(x4, we, se4);
        sa01 = ffma2(x01, wa2, sa01);
        sa23 = ffma2(x23, wa2, sa23);
        sa4  = fmaf(x4, wa, sa4);
    }
    float2 s01 = u2f(se01), s23 = u2f(se23);
    float2 a01 = u2f(sa01), a23 = u2f(sa23);
    float er[5] = {s01.x, s01.y, s23.x, s23.y, se4};
    float ar[5] = {a01.x, a01.y, a23.x, a23.y, sa4};
    #pragma unroll
    for (int r = 0; r < 5; r++) {
        float e = 1.f / (1.f + expf(-er[r]));
        float a = tanhf(ar[r]);
        g_ea[(q * 5 + r) * 128 + v] = make_float4(-e, -e, a, a);
    }
}

// ---------------- kernel W: pack summary_w / theta_w ----------------
__global__ void kW(const float* __restrict__ sw, const float* __restrict__ tw) {
    int idx = blockIdx.x * blockDim.x + threadIdx.x;
    if (idx < DV * 32) {
        int v = idx >> 5, jp = idx & 31;
        int j0 = 2 * jp, j1 = 2 * jp + 1;
        float w0 = (j0 < 50) ? sw[v * 50 + j0] : 0.f;
        float w1 = (j1 < 50) ? sw[v * 50 + j1] : 0.f;
        ((float2*)g_wt2)[idx] = make_float2(w0, w1);
    } else if (idx < DV * 32 + 64) {
        int j = idx - DV * 32;
        g_thw[j] = (j < 50) ? tw[j] : 0.f;
    }
}

// ---------------- scan kernel: cp.async 4-stage per-warp pipeline ----------------
__global__ void __launch_bounds__(128) kScan(const float* __restrict__ init_mem,
                                             const int* __restrict__ questions,
                                             const int* __restrict__ responses) {
    __shared__ int2 s_off[SS];                      // 16KB
    __shared__ alignas(16) float s_attn[4][STAGES][64];  // 4KB, per-warp stages
    int b = blockIdx.x, v = threadIdx.x;
    int w = v >> 5, lane = v & 31;

    // build per-step offsets locally (formerly kernel kC)
    const int* qp = questions + b * SS;
    const int* rp = responses + b * SS;
    for (int i = v; i < SS; i += 128) {
        int q = qp[i], r = rp[i];
        s_off[i] = make_int2(q * 52, (q * 5 + r) * 128);
    }

    ull mem2[25];
    #pragma unroll
    for (int i = 0; i < 25; i++)
        mem2[i] = pack2(init_mem[(2 * i) * DV + v], init_mem[(2 * i + 1) * DV + v]);
    __syncthreads();

    // prologue: stages 0..2 hold steps 0..2
    float4 ea[STAGES];
    #pragma unroll
    for (int st = 0; st < 3; st++) {
        int2 o = s_off[st];
        if (lane < 13) cp16(&s_attn[w][st][lane * 4], g_attn + o.x + lane * 4);
        asm volatile("cp.async.commit_group;");
        ea[st] = __ldg(&g_ea[o.y + v]);
    }

    int2 og[STAGES];
    #pragma unroll
    for (int u = 0; u < STAGES; u++) {
        int fs = u + 3; if (fs > SS - 1) fs = SS - 1;
        og[u] = s_off[fs];
    }

    float* outp = g_read + (size_t)b * SS * DV + v;

    #pragma unroll 1
    for (int s = 0; s < SS; s += STAGES) {
        int2 ogn[STAGES];
        #pragma unroll
        for (int u = 0; u < STAGES; u++) {
            int fs = s + u + 3 + STAGES; if (fs > SS - 1) fs = SS - 1;
            ogn[u] = s_off[fs];
        }
        #pragma unroll
        for (int u = 0; u < STAGES; u++) {
            int2 o = og[u];                      // offsets for step s+u+3
            int pst = (u + 3) & 3;
            if (lane < 13) cp16(&s_attn[w][pst][lane * 4], g_attn + o.x + lane * 4);
            asm volatile("cp.async.commit_group;");
            float4 ean = __ldg(&g_ea[o.y + v]);
            asm volatile("cp.async.wait_group 3;");

            // compute step s+u from stage u
            float4 ec = ea[u];
            ull e2 = pack2(ec.x, ec.y);          // (-e,-e)
            ull d2 = pack2(ec.z, ec.w);          // (a,a)
            ull r0 = 0ull, r1 = 0ull;
            const ull* ap = (const ull*)s_attn[w][u];
            #pragma unroll
            for (int i = 0; i < 25; i++) {
                ull ai = ap[i];                  // LDS.64 broadcast
                if (i & 1) r1 = ffma2(ai, mem2[i], r1);
                else       r0 = ffma2(ai, mem2[i], r0);
                ull t = ffma2(e2, mem2[i], d2);  // add - erase*mem
                mem2[i] = ffma2(ai, t, mem2[i]); // mem += attn*t
            }
            ea[pst] = ean;
            float2 f0 = u2f(r0), f1 = u2f(r1);
            __stcs(outp + (s + u) * DV, (f0.x + f1.x) + (f0.y + f1.y));
        }
        #pragma unroll
        for (int u = 0; u < STAGES; u++) og[u] = ogn[u];
    }
    asm volatile("cp.async.wait_group 0;");
}

// ---------------- epilogue kernel ----------------
#define NPOS (BB * SS)
#define OFF_THETA  0
#define OFF_ALPHA  (NPOS)
#define OFF_BETA   (2 * NPOS)
#define OFF_LOGITS (6 * NPOS)
#define OFF_PROBS  (11 * NPOS)

__global__ void __launch_bounds__(128) kEpi(const int* __restrict__ questions,
                                            const float* __restrict__ theta_b,
                                            float* __restrict__ out) {
    int tid = threadIdx.x;
    int pt = tid >> 3;        // 0..15, 4 positions each
    int jt = tid & 7;         // 0..7, 4 j-pairs each (covers j 0..63, padded)
    int pos0 = blockIdx.x * 64 + pt * 4;

    ull acc[4][4];
    #pragma unroll
    for (int k = 0; k < 4; k++)
        #pragma unroll
        for (int c = 0; c < 4; c++) acc[k][c] = 0ull;

    const float4* rp0 = (const float4*)(g_read + (size_t)(pos0 + 0) * DV);
    const float4* rp1 = (const float4*)(g_read + (size_t)(pos0 + 1) * DV);
    const float4* rp2 = (const float4*)(g_read + (size_t)(pos0 + 2) * DV);
    const float4* rp3 = (const float4*)(g_read + (size_t)(pos0 + 3) * DV);

    #pragma unroll 4
    for (int v4 = 0; v4 < 32; v4++) {
        float4 rd[4];
        rd[0] = __ldg(rp0 + v4);
        rd[1] = __ldg(rp1 + v4);
        rd[2] = __ldg(rp2 + v4);
        rd[3] = __ldg(rp3 + v4);
        #pragma unroll
        for (int d = 0; d < 4; d++) {
            int v = v4 * 4 + d;
            const ulonglong2* wr = (const ulonglong2*)(g_wt2 + v * 32 + jt * 4);
            ulonglong2 wA = __ldg(wr);
            ulonglong2 wB = __ldg(wr + 1);
            #pragma unroll
            for (int k = 0; k < 4; k++) {
                float rv = ((const float*)&rd[k])[d];
                ull rvv = pack2(rv, rv);
                acc[k][0] = ffma2(rvv, wA.x, acc[k][0]);
                acc[k][1] = ffma2(rvv, wA.y, acc[k][1]);
                acc[k][2] = ffma2(rvv, wB.x, acc[k][2]);
                acc[k][3] = ffma2(rvv, wB.y, acc[k][3]);
            }
        }
    }

    float tb = __ldg(theta_b);
    #pragma unroll
    for (int k = 0; k < 4; k++) {
        int pos = pos0 + k;
        int q = __ldg(questions + pos);
        const ull* qs2 = ((const ull*)g_qsum) + q * 32 + jt * 4;
        float th = 0.f;
        #pragma unroll
        for (int c = 0; c < 4; c++) {
            float2 s2 = u2f(acc[k][c]);
            float2 qv = u2f(__ldg(qs2 + c));
            int jp = jt * 4 + c;
            float s0 = tanh_fast(s2.x + qv.x);
            float s1 = tanh_fast(s2.y + qv.y);
            th += s0 * g_thw[2 * jp] + s1 * g_thw[2 * jp + 1];
        }
        th += __shfl_xor_sync(0xffffffffu, th, 1);
        th += __shfl_xor_sync(0xffffffffu, th, 2);
        th += __shfl_xor_sync(0xffffffffu, th, 4);
        if (jt == 0) {
            float theta = tanhf(th + tb);
            float alpha = __ldg(g_alpha + q);
            float4 bv = __ldg((const float4*)(g_beta + q * 4));
            float it = theta * alpha;
            float l0 = 0.f;
            float l1 = it - bv.x;
            float l2 = l1 + it - bv.y;
            float l3 = l2 + it - bv.z;
            float l4 = l3 + it - bv.w;
            float m = fmaxf(fmaxf(fmaxf(l0, l1), fmaxf(l2, l3)), l4);
            float e0 = __expf(l0 - m), e1 = __expf(l1 - m), e2 = __expf(l2 - m),
                  e3 = __expf(l3 - m), e4 = __expf(l4 - m);
            float inv = 1.f / (e0 + e1 + e2 + e3 + e4);
            out[OFF_THETA + pos] = theta;
            out[OFF_ALPHA + pos] = alpha;
            ((float4*)(out + OFF_BETA))[pos] = bv;
            float* lo = out + OFF_LOGITS + pos * 5;
            lo[0] = l0; lo[1] = l1; lo[2] = l2; lo[3] = l3; lo[4] = l4;
            float* pr = out + OFF_PROBS + pos * 5;
            pr[0] = e0 * inv; pr[1] = e1 * inv; pr[2] = e2 * inv;
            pr[3] = e3 * inv; pr[4] = e4 * inv;
        }
    }
}

// ---------------- launch ----------------
extern "C" void kernel_launch(void* const* d_in, const int* in_sizes, int n_in,
                              void* d_out, int out_size) {
    const int*   questions    = (const int*)d_in[0];
    const int*   responses    = (const int*)d_in[1];
    const float* q_embed_w    = (const float*)d_in[2];
    const float* item_embed_w = (const float*)d_in[3];
    const float* value_proj_w = (const float*)d_in[4];
    const float* value_proj_b = (const float*)d_in[5];
    const float* key_mem      = (const float*)d_in[6];
    const float* init_mem     = (const float*)d_in[7];
    const float* erase_w      = (const float*)d_in[8];
    const float* erase_b      = (const float*)d_in[9];
    const float* add_w        = (const float*)d_in[10];
    const float* add_b        = (const float*)d_in[11];
    const float* summary_w    = (const float*)d_in[12];
    const float* summary_b    = (const float*)d_in[13];
    const float* theta_w      = (const float*)d_in[14];
    const float* theta_b      = (const float*)d_in[15];
    const float* alpha_w      = (const float*)d_in[16];
    const float* alpha_b      = (const float*)d_in[17];
    const float* beta_w       = (const float*)d_in[18];
    const float* beta_b       = (const float*)d_in[19];
    float* out = (float*)d_out;

    kA<<<QQ, 64>>>(q_embed_w, key_mem, summary_w, summary_b,
                   alpha_w, alpha_b, beta_w, beta_b);
    kB<<<QQ, 128>>>(item_embed_w, value_proj_w, value_proj_b,
                    erase_w, erase_b, add_w, add_b);
    kW<<<(DV * 32 + 64 + 255) / 256, 256>>>(summary_w, theta_w);
    kScan<<<BB, 128>>>(init_mem, questions, responses);
    kEpi<<<(BB * SS) / 64, 128>>>(questions, theta_b, out);
}